// round 13
// baseline (speedup 1.0000x reference)
#include <cuda_runtime.h>

// Fully fused shift + H-conv(128->8 via w1) + W-conv(8->128 via w2), (1,128,56,56) fp32.
// v11 = v10 with NO weight staging: w1/w2 read directly via __ldg (warp-uniform broadcast
// L1 hits), which deletes the staging segment and the first __syncthreads (3 -> 2 barriers).
// Grid (2,56) = 112 blocks x 512 threads (1/SM, single wave).
//
// Stage 1: inter[k4][o][n] = sum_{i<64,j<3} w1[k4,i,j] * X(2i+o, m+j-1, n)
//   X(c,h,n) = x[c][(h-1+56)%56][n] if 0<=h<56 else 0  (roll(+1) in H, zero-pad H)
// Stage 2: out[i32*4+k4][m][n] = sum_{o,kk} w2[i32,o,kk] * inter[k4][o][n+kk-1]  (zero-pad W)

#define HH 56
#define WW 56
#define NF4B 8            // float4 columns per block (32 cols incl. halo)
#define TNO 28            // output cols per block
#define THREADS 512       // 64 go-groups x 8 f4-columns

__global__ __launch_bounds__(THREADS)
void fused_shift_conv_v11(const float* __restrict__ x,
                          const float* __restrict__ w1,
                          const float* __restrict__ w2,
                          float* __restrict__ out)
{
    __shared__ float psum[128 * 32];         // [(gr*2+o)*4+k][local col]  16 KB
    __shared__ float inter_s[8 * 34];        // [o*4+k][local col + 1], idx 0 & 33 = zero halo

    const int tid = threadIdx.x;
    const int h   = blockIdx.x;              // 0..1 (n-half)
    const int m   = blockIdx.y;              // 0..55
    const int s4  = h * 6;                   // first global float4 col (0 or 6)
    const int nb  = h * TNO;                 // first output col (0 or 28)
    const int lshift = h * 4;                // local col = n2 + lshift

    const int f4l = tid & (NF4B - 1);        // local float4 col 0..7
    const int go  = tid >> 3;                // 0..63 = ig*2 + o
    const int o   = go & 1;
    const int ig  = go >> 1;                 // 0..31, 2 i-values each

    // H taps: rolled source rows + validity masks (uniform per block)
    float msk[3];
    int   h14[3];
    #pragma unroll
    for (int j = 0; j < 3; ++j) {
        const int hh = m + j - 1;                     // pre-roll coordinate
        msk[j] = (hh >= 0 && hh < HH) ? 1.f : 0.f;
        h14[j] = ((hh + 55) % HH) * 14;               // rolled row offset, float4 units
    }

    // ---- prefetch x: 6 independent LDG.128 ----
    const float4* __restrict__ x4 = (const float4*)x;
    float4 xv[2][3];
    #pragma unroll
    for (int ii = 0; ii < 2; ++ii) {
        const int c = 2 * (ig * 2 + ii) + o;
        const float4* xb = x4 + c * (HH * 14) + s4 + f4l;
        #pragma unroll
        for (int j = 0; j < 3; ++j)
            xv[ii][j] = __ldg(xb + h14[j]);
    }

    // fold H masks into the loaded values (overlaps load latency)
    #pragma unroll
    for (int ii = 0; ii < 2; ++ii)
        #pragma unroll
        for (int j = 0; j < 3; ++j) {
            xv[ii][j].x *= msk[j];
            xv[ii][j].y *= msk[j];
            xv[ii][j].z *= msk[j];
            xv[ii][j].w *= msk[j];
        }

    // ---------------- Phase 1: 96 FMAs, weights via uniform __ldg ----------------
    float4 acc[4];
    #pragma unroll
    for (int k = 0; k < 4; ++k) acc[k] = make_float4(0.f, 0.f, 0.f, 0.f);

    #pragma unroll
    for (int ii = 0; ii < 2; ++ii) {
        const float* wb = w1 + (ig * 2 + ii) * 3;     // 16 lanes share this base
        #pragma unroll
        for (int j = 0; j < 3; ++j) {
            const float4 v = xv[ii][j];
            #pragma unroll
            for (int k = 0; k < 4; ++k) {
                const float w = __ldg(wb + k * 192 + j);
                acc[k].x = fmaf(w, v.x, acc[k].x);
                acc[k].y = fmaf(w, v.y, acc[k].y);
                acc[k].z = fmaf(w, v.z, acc[k].z);
                acc[k].w = fmaf(w, v.w, acc[k].w);
            }
        }
    }

    // ---- shfl pre-reduction: combine ig pairs (ig ^ 1), same o & f4l ----
    // go differs by 2 -> tid differs by 16 -> same warp
    #pragma unroll
    for (int k = 0; k < 4; ++k) {
        acc[k].x += __shfl_xor_sync(0xffffffffu, acc[k].x, 16);
        acc[k].y += __shfl_xor_sync(0xffffffffu, acc[k].y, 16);
        acc[k].z += __shfl_xor_sync(0xffffffffu, acc[k].z, 16);
        acc[k].w += __shfl_xor_sync(0xffffffffu, acc[k].w, 16);
    }
    if (((tid >> 4) & 1) == 0) {             // ig even: store pair sum
        const int gr = ig >> 1;              // reduced group 0..15
        float4* ps4 = (float4*)psum;
        #pragma unroll
        for (int k = 0; k < 4; ++k)
            ps4[((gr * 2 + o) * 4 + k) * NF4B + f4l] = acc[k];
    }
    __syncthreads();

    // ---- reduce 16 groups per (o,k,local col): 256 threads, one output each ----
    if (tid < 256) {
        const int ll = tid & 31;             // local col 0..31
        const int ok = tid >> 5;             // o*4 + k
        const int oo = ok >> 2;
        const int k  = ok & 3;
        float ssum = 0.f;
        #pragma unroll
        for (int g = 0; g < 16; ++g)
            ssum += psum[((g * 2 + oo) * 4 + k) * 32 + ll];
        inter_s[ok * 34 + ll + 1] = ssum;
        if (tid < 16)                        // zero halo at padded idx 0 and 33
            inter_s[(tid >> 1) * 34 + (tid & 1) * 33] = 0.f;
    }
    __syncthreads();

    // ---------------- Phase 2: float4 outputs, 896 quads, 2 per thread ----------------
    if (tid < 448) {
        float4* __restrict__ out4 = (float4*)out;
        #pragma unroll
        for (int t = 0; t < 2; ++t) {
            const int q   = tid + t * 448;   // 0..895
            const int f4o = q % 7;           // output quad within half-row
            const int co  = q / 7;           // 0..127 = i32*4 + k4
            const int i32 = co >> 2;
            const int k4  = co & 3;
            const int n0  = f4o * 4;         // local output col base

            const float* wb = w2 + i32 * 6;  // warp-uniform broadcast loads
            float4 a = make_float4(0.f, 0.f, 0.f, 0.f);
            #pragma unroll
            for (int oo = 0; oo < 2; ++oo) {
                const float* ib = inter_s + (oo * 4 + k4) * 34 + n0 + lshift;  // taps +0..+5
                const float s0 = ib[0], s1 = ib[1], s2 = ib[2],
                            s3 = ib[3], s4v = ib[4], s5 = ib[5];
                const float wA = __ldg(wb + oo * 3 + 0);
                const float wB = __ldg(wb + oo * 3 + 1);
                const float wC = __ldg(wb + oo * 3 + 2);
                a.x = fmaf(wA, s0, fmaf(wB, s1, fmaf(wC, s2, a.x)));
                a.y = fmaf(wA, s1, fmaf(wB, s2, fmaf(wC, s3, a.y)));
                a.z = fmaf(wA, s2, fmaf(wB, s3, fmaf(wC, s4v, a.z)));
                a.w = fmaf(wA, s3, fmaf(wB, s4v, fmaf(wC, s5, a.w)));
            }
            out4[(co * (HH * WW) + m * WW + nb + n0) >> 2] = a;
        }
    }
}

extern "C" void kernel_launch(void* const* d_in, const int* in_sizes, int n_in,
                              void* d_out, int out_size)
{
    const float* x  = (const float*)d_in[0];   // (1,128,56,56)
    const float* w1 = (const float*)d_in[1];   // (4,64,3)
    const float* w2 = (const float*)d_in[2];   // (32,2,3)
    float* out = (float*)d_out;                // (1,128,56,56)

    dim3 grid(2, HH);                          // 112 blocks
    fused_shift_conv_v11<<<grid, THREADS>>>(x, w1, w2, out);
}

// round 14
// speedup vs baseline: 1.2977x; 1.2977x over previous
#include <cuda_runtime.h>

// Fully fused shift + H-conv(128->8 via w1) + W-conv(8->128 via w2), (1,128,56,56) fp32.
// v12 = v10 with per-warp w1 staging (masks folded) + __syncwarp instead of block
// barrier #1: each warp stages its own 48 weights and starts FMAs independently.
// Grid (2,56) = 112 blocks x 512 threads (1/SM, single wave). 2 block barriers.
//
// Stage 1: inter[k4][o][n] = sum_{i<64,j<3} w1[k4,i,j] * X(2i+o, m+j-1, n)
//   X(c,h,n) = x[c][(h-1+56)%56][n] if 0<=h<56 else 0  (roll(+1) in H, zero-pad H)
// Stage 2: out[i32*4+k4][m][n] = sum_{o,kk} w2[i32,o,kk] * inter[k4][o][n+kk-1]  (zero-pad W)

#define HH 56
#define WW 56
#define NF4B 8            // float4 columns per block (32 cols incl. halo)
#define TNO 28            // output cols per block
#define THREADS 512       // 64 go-groups x 8 f4-columns

__global__ __launch_bounds__(THREADS)
void fused_shift_conv_v12(const float* __restrict__ x,
                          const float* __restrict__ w1,
                          const float* __restrict__ w2,
                          float* __restrict__ out)
{
    __shared__ float w1w[16 * 48];           // per-warp w1 slices [w][k4][il4][j3], masks folded
    __shared__ float w2s[192];               // [i32][o2][kk3]
    __shared__ float psum[128 * 32];         // [(gr*2+o)*4+k][local col]  16 KB
    __shared__ float inter_s[8 * 34];        // [o*4+k][local col + 1], idx 0 & 33 = zero halo

    const int tid  = threadIdx.x;
    const int lane = tid & 31;
    const int w    = tid >> 5;               // warp 0..15
    const int h    = blockIdx.x;             // 0..1 (n-half)
    const int m    = blockIdx.y;             // 0..55
    const int s4   = h * 6;                  // first global float4 col (0 or 6)
    const int nb   = h * TNO;                // first output col (0 or 28)
    const int lshift = h * 4;                // local col = n2 + lshift

    const int f4l = tid & (NF4B - 1);        // local float4 col 0..7
    const int go  = tid >> 3;                // 0..63 = ig*2 + o
    const int o   = go & 1;
    const int ig  = go >> 1;                 // 0..31, 2 i-values each

    // H taps: rolled source rows + validity masks (uniform per block)
    float msk[3];
    int   h14[3];
    #pragma unroll
    for (int j = 0; j < 3; ++j) {
        const int hh = m + j - 1;                     // pre-roll coordinate
        msk[j] = (hh >= 0 && hh < HH) ? 1.f : 0.f;
        h14[j] = ((hh + 55) % HH) * 14;               // rolled row offset, float4 units
    }

    // ---- prefetch x: 6 independent LDG.128 ----
    const float4* __restrict__ x4 = (const float4*)x;
    float4 xv[2][3];
    #pragma unroll
    for (int ii = 0; ii < 2; ++ii) {
        const int c = 2 * (ig * 2 + ii) + o;
        const float4* xb = x4 + c * (HH * 14) + s4 + f4l;
        #pragma unroll
        for (int j = 0; j < 3; ++j)
            xv[ii][j] = __ldg(xb + h14[j]);
    }

    // ---- per-warp w1 staging: warp w needs i in [4w, 4w+4), all k4, masks folded ----
    // 48 floats per warp: t = k4*12 + r, r = il*3 + j ; gmem idx = k4*192 + w*12 + r
    #pragma unroll
    for (int t = lane; t < 48; t += 32) {
        const int k4i = t / 12;
        const int r   = t - k4i * 12;
        w1w[w * 48 + t] = w1[k4i * 192 + w * 12 + r] * msk[r % 3];
    }
    // ---- w2 staging (visibility guaranteed by the psum barrier below) ----
    if (tid < 192) w2s[tid] = w2[tid];
    __syncwarp();

    // ---------------- Phase 1: 96 FMAs from registers + warp-local smem weights ----------------
    float4 acc[4];
    #pragma unroll
    for (int k = 0; k < 4; ++k) acc[k] = make_float4(0.f, 0.f, 0.f, 0.f);

    const int ilbase = 2 * ((tid >> 4) & 1); // il = ilbase + ii
    const float* wbase = w1w + w * 48;
    #pragma unroll
    for (int ii = 0; ii < 2; ++ii) {
        const float* wb = wbase + (ilbase + ii) * 3;
        #pragma unroll
        for (int j = 0; j < 3; ++j) {
            const float4 v = xv[ii][j];
            #pragma unroll
            for (int k = 0; k < 4; ++k) {
                const float ww = wb[k * 12 + j];
                acc[k].x = fmaf(ww, v.x, acc[k].x);
                acc[k].y = fmaf(ww, v.y, acc[k].y);
                acc[k].z = fmaf(ww, v.z, acc[k].z);
                acc[k].w = fmaf(ww, v.w, acc[k].w);
            }
        }
    }

    // ---- shfl pre-reduction: combine ig pairs (ig ^ 1), same o & f4l ----
    // go differs by 2 -> tid differs by 16 -> same warp
    #pragma unroll
    for (int k = 0; k < 4; ++k) {
        acc[k].x += __shfl_xor_sync(0xffffffffu, acc[k].x, 16);
        acc[k].y += __shfl_xor_sync(0xffffffffu, acc[k].y, 16);
        acc[k].z += __shfl_xor_sync(0xffffffffu, acc[k].z, 16);
        acc[k].w += __shfl_xor_sync(0xffffffffu, acc[k].w, 16);
    }
    if (((tid >> 4) & 1) == 0) {             // ig even: store pair sum
        const int gr = ig >> 1;              // reduced group 0..15
        float4* ps4 = (float4*)psum;
        #pragma unroll
        for (int k = 0; k < 4; ++k)
            ps4[((gr * 2 + o) * 4 + k) * NF4B + f4l] = acc[k];
    }
    __syncthreads();

    // ---- reduce 16 groups per (o,k,local col): 256 threads, one output each ----
    if (tid < 256) {
        const int ll = tid & 31;             // local col 0..31
        const int ok = tid >> 5;             // o*4 + k
        const int oo = ok >> 2;
        const int k  = ok & 3;
        float ssum = 0.f;
        #pragma unroll
        for (int g = 0; g < 16; ++g)
            ssum += psum[((g * 2 + oo) * 4 + k) * 32 + ll];
        inter_s[ok * 34 + ll + 1] = ssum;
        if (tid < 16)                        // zero halo at padded idx 0 and 33
            inter_s[(tid >> 1) * 34 + (tid & 1) * 33] = 0.f;
    }
    __syncthreads();

    // ---------------- Phase 2: float4 outputs, 896 quads, 2 per thread ----------------
    if (tid < 448) {
        float4* __restrict__ out4 = (float4*)out;
        #pragma unroll
        for (int t = 0; t < 2; ++t) {
            const int q   = tid + t * 448;   // 0..895
            const int f4o = q % 7;           // output quad within half-row
            const int co  = q / 7;           // 0..127 = i32*4 + k4
            const int i32 = co >> 2;
            const int k4  = co & 3;
            const int n0  = f4o * 4;         // local output col base

            const float* wb = w2s + i32 * 6;
            float4 a = make_float4(0.f, 0.f, 0.f, 0.f);
            #pragma unroll
            for (int oo = 0; oo < 2; ++oo) {
                const float* ib = inter_s + (oo * 4 + k4) * 34 + n0 + lshift;  // taps +0..+5
                const float s0 = ib[0], s1 = ib[1], s2 = ib[2],
                            s3 = ib[3], s4v = ib[4], s5 = ib[5];
                const float wA = wb[oo * 3 + 0];
                const float wB = wb[oo * 3 + 1];
                const float wC = wb[oo * 3 + 2];
                a.x = fmaf(wA, s0, fmaf(wB, s1, fmaf(wC, s2, a.x)));
                a.y = fmaf(wA, s1, fmaf(wB, s2, fmaf(wC, s3, a.y)));
                a.z = fmaf(wA, s2, fmaf(wB, s3, fmaf(wC, s4v, a.z)));
                a.w = fmaf(wA, s3, fmaf(wB, s4v, fmaf(wC, s5, a.w)));
            }
            out4[(co * (HH * WW) + m * WW + nb + n0) >> 2] = a;
        }
    }
}

extern "C" void kernel_launch(void* const* d_in, const int* in_sizes, int n_in,
                              void* d_out, int out_size)
{
    const float* x  = (const float*)d_in[0];   // (1,128,56,56)
    const float* w1 = (const float*)d_in[1];   // (4,64,3)
    const float* w2 = (const float*)d_in[2];   // (32,2,3)
    float* out = (float*)d_out;                // (1,128,56,56)

    dim3 grid(2, HH);                          // 112 blocks
    fused_shift_conv_v12<<<grid, THREADS>>>(x, w1, w2, out);
}